// round 5
// baseline (speedup 1.0000x reference)
#include <cuda_runtime.h>

#define NT   262144
#define KC   512
#define DD   64
#define TPB  256
#define TOKENS_PER_BLOCK (TPB * 2)
#define GRID (NT / TOKENS_PER_BLOCK)
#define SMEM_BYTES ((KC * DD + KC) * 4)

typedef unsigned long long u64;

__device__ double g_loss_acc;          // zero-init; reset by last block each run
__device__ unsigned int g_done_ctr;    // zero-init; reset by last block each run

// Packed 2-wide fp32 FMA (Blackwell FFMA2)
__device__ __forceinline__ u64 ffma2(u64 a, u64 b, u64 c) {
    u64 d;
    asm("fma.rn.f32x2 %0, %1, %2, %3;" : "=l"(d) : "l"(a), "l"(b), "l"(c));
    return d;
}

__device__ __forceinline__ float2 unpack2(u64 v) {
    float2 r;
    asm("mov.b64 {%0, %1}, %2;" : "=f"(r.x), "=f"(r.y) : "l"(v));
    return r;
}

// Branchless top-3 ascending insert (values v[0..2], indices ix[0..2])
__device__ __forceinline__ void top3(float s, int kk, float* v, int* ix) {
    bool lt0 = s < v[0], lt1 = s < v[1], lt2 = s < v[2];
    float nv2 = lt2 ? (lt1 ? v[1] : s) : v[2];
    int   ni2 = lt2 ? (lt1 ? ix[1] : kk) : ix[2];
    float nv1 = lt1 ? (lt0 ? v[0] : s) : v[1];
    int   ni1 = lt1 ? (lt0 ? ix[0] : kk) : ix[1];
    float nv0 = lt0 ? s : v[0];
    int   ni0 = lt0 ? kk : ix[0];
    v[0] = nv0; v[1] = nv1; v[2] = nv2;
    ix[0] = ni0; ix[1] = ni1; ix[2] = ni2;
}

__global__ void __launch_bounds__(TPB) vq_fused(const float* __restrict__ z,
                                                const float* __restrict__ cb,
                                                float* __restrict__ out,
                                                int loss_idx) {
    extern __shared__ float sm[];
    float* s_cb = sm;             // [KC*DD] codebook fp32
    float* s_c2 = sm + KC * DD;   // [KC] squared norms
    __shared__ double s_red[TPB / 32];

    // Cooperative codebook load
    for (int i = threadIdx.x; i < KC * DD / 4; i += TPB)
        ((float4*)s_cb)[i] = ((const float4*)cb)[i];
    __syncthreads();

    // Per-code squared norms (sequential fp32 FMA; matches passing R2/R4)
    for (int k = threadIdx.x; k < KC; k += TPB) {
        const float* row = s_cb + k * DD;
        float s = 0.0f;
#pragma unroll
        for (int d = 0; d < DD; ++d) s = __fmaf_rn(row[d], row[d], s);
        s_c2[k] = s;
    }
    __syncthreads();

    // Two tokens per thread, TPB-strided for coalesced gmem access
    const int tok0 = blockIdx.x * TOKENS_PER_BLOCK + threadIdx.x;
    const int tok1 = tok0 + TPB;

    u64 zq0[DD / 2], zq1[DD / 2];
    {
        const ulonglong2* zp0 = (const ulonglong2*)(z + (size_t)tok0 * DD);
        const ulonglong2* zp1 = (const ulonglong2*)(z + (size_t)tok1 * DD);
#pragma unroll
        for (int i = 0; i < DD / 4; ++i) {
            ulonglong2 a = zp0[i];
            zq0[2 * i] = a.x; zq0[2 * i + 1] = a.y;
            ulonglong2 b = zp1[i];
            zq1[2 * i] = b.x; zq1[2 * i + 1] = b.y;
        }
    }

    // ---- Filter: approx score fl(c2_k - fl(2*dot_k)) via packed FFMA2.
    // Deviation vs exact is packed-accumulation order only (~1e-7), << typical
    // 1st-2nd gap (~6e-3). Top-3 + exact rescore covers quantized tie buckets.
    const float FINF = __int_as_float(0x7f800000);
    float v0[3] = {FINF, FINF, FINF}, v1[3] = {FINF, FINF, FINF};
    int   x0[3] = {0, 0, 0},          x1[3] = {0, 0, 0};

#pragma unroll 1
    for (int k = 0; k < KC; k += 4) {
        u64 a00 = 0ull, a01 = 0ull, a02 = 0ull, a03 = 0ull;  // token0
        u64 a10 = 0ull, a11 = 0ull, a12 = 0ull, a13 = 0ull;  // token1
        const ulonglong2* r0 = (const ulonglong2*)(s_cb + (k + 0) * DD);
        const ulonglong2* r1 = (const ulonglong2*)(s_cb + (k + 1) * DD);
        const ulonglong2* r2 = (const ulonglong2*)(s_cb + (k + 2) * DD);
        const ulonglong2* r3 = (const ulonglong2*)(s_cb + (k + 3) * DD);
#pragma unroll
        for (int i = 0; i < DD / 4; ++i) {
            ulonglong2 ca = r0[i], cbv = r1[i], cc = r2[i], cd = r3[i];
            u64 zl0 = zq0[2 * i], zh0 = zq0[2 * i + 1];
            u64 zl1 = zq1[2 * i], zh1 = zq1[2 * i + 1];
            a00 = ffma2(ca.x,  zl0, a00); a00 = ffma2(ca.y,  zh0, a00);
            a01 = ffma2(cbv.x, zl0, a01); a01 = ffma2(cbv.y, zh0, a01);
            a02 = ffma2(cc.x,  zl0, a02); a02 = ffma2(cc.y,  zh0, a02);
            a03 = ffma2(cd.x,  zl0, a03); a03 = ffma2(cd.y,  zh0, a03);
            a10 = ffma2(ca.x,  zl1, a10); a10 = ffma2(ca.y,  zh1, a10);
            a11 = ffma2(cbv.x, zl1, a11); a11 = ffma2(cbv.y, zh1, a11);
            a12 = ffma2(cc.x,  zl1, a12); a12 = ffma2(cc.y,  zh1, a12);
            a13 = ffma2(cd.x,  zl1, a13); a13 = ffma2(cd.y,  zh1, a13);
        }
        float c2a = s_c2[k + 0], c2b = s_c2[k + 1], c2c = s_c2[k + 2], c2d = s_c2[k + 3];
        float2 p;
        p = unpack2(a00); top3(__fsub_rn(c2a, __fmul_rn(2.0f, __fadd_rn(p.x, p.y))), k + 0, v0, x0);
        p = unpack2(a01); top3(__fsub_rn(c2b, __fmul_rn(2.0f, __fadd_rn(p.x, p.y))), k + 1, v0, x0);
        p = unpack2(a02); top3(__fsub_rn(c2c, __fmul_rn(2.0f, __fadd_rn(p.x, p.y))), k + 2, v0, x0);
        p = unpack2(a03); top3(__fsub_rn(c2d, __fmul_rn(2.0f, __fadd_rn(p.x, p.y))), k + 3, v0, x0);
        p = unpack2(a10); top3(__fsub_rn(c2a, __fmul_rn(2.0f, __fadd_rn(p.x, p.y))), k + 0, v1, x1);
        p = unpack2(a11); top3(__fsub_rn(c2b, __fmul_rn(2.0f, __fadd_rn(p.x, p.y))), k + 1, v1, x1);
        p = unpack2(a12); top3(__fsub_rn(c2c, __fmul_rn(2.0f, __fadd_rn(p.x, p.y))), k + 2, v1, x1);
        p = unpack2(a13); top3(__fsub_rn(c2d, __fmul_rn(2.0f, __fadd_rn(p.x, p.y))), k + 3, v1, x1);
    }

    // ---- Exact rescore (reference rounding: fl(fl(S+c2)-fl(2*dot)),
    //      sequential fp32 FMA, first-index tie-break) + epilogue, per token.
    double dacc = 0.0;
    {
        const u64* zqs[2] = {zq0, zq1};
        const int  toks[2] = {tok0, tok1};
        float* vs[2] = {v0, v1};
        int*   xs[2] = {x0, x1};
#pragma unroll
        for (int t = 0; t < 2; ++t) {
            const u64* zq = zqs[t];
            float S = 0.0f;
#pragma unroll
            for (int i = 0; i < DD / 2; ++i) {
                float2 pz = unpack2(zq[i]);
                S = __fmaf_rn(pz.x, pz.x, S);
                S = __fmaf_rn(pz.y, pz.y, S);
            }
            int   bestk = xs[t][0];
            float bests = FINF;
#pragma unroll
            for (int c = 0; c < 3; ++c) {
                const int kk = xs[t][c];
                const float* rw = s_cb + kk * DD;
                float d = 0.0f;
#pragma unroll
                for (int i = 0; i < DD / 2; ++i) {
                    float2 pz = unpack2(zq[i]);
                    d = __fmaf_rn(rw[2 * i], pz.x, d);
                    d = __fmaf_rn(rw[2 * i + 1], pz.y, d);
                }
                float e = __fsub_rn(__fadd_rn(S, s_c2[kk]), __fmul_rn(2.0f, d));
                if (e < bests || (e == bests && kk < bestk)) { bests = e; bestk = kk; }
            }
            // z_q_st = fl(z + fl(z_q - z)); loss partial = sum fl(z_q - z)^2
            const float4* q = (const float4*)(s_cb + bestk * DD);
            float4* op = (float4*)(out + (size_t)toks[t] * DD);
            float lacc = 0.0f;
#pragma unroll
            for (int i = 0; i < DD / 4; ++i) {
                float4 c = q[i];
                float2 plo = unpack2(zq[2 * i]);
                float2 phi = unpack2(zq[2 * i + 1]);
                float4 o; float dx;
                dx = __fsub_rn(c.x, plo.x); o.x = __fadd_rn(plo.x, dx); lacc = __fmaf_rn(dx, dx, lacc);
                dx = __fsub_rn(c.y, plo.y); o.y = __fadd_rn(plo.y, dx); lacc = __fmaf_rn(dx, dx, lacc);
                dx = __fsub_rn(c.z, phi.x); o.z = __fadd_rn(phi.x, dx); lacc = __fmaf_rn(dx, dx, lacc);
                dx = __fsub_rn(c.w, phi.y); o.w = __fadd_rn(phi.y, dx); lacc = __fmaf_rn(dx, dx, lacc);
                op[i] = o;
            }
            dacc += (double)lacc;
        }
    }

    // Block reduce (double) -> global atomic -> last block finalizes + resets
#pragma unroll
    for (int o = 16; o > 0; o >>= 1)
        dacc += __shfl_down_sync(0xFFFFFFFFu, dacc, o);
    const int lane = threadIdx.x & 31;
    const int warp = threadIdx.x >> 5;
    if (lane == 0) s_red[warp] = dacc;
    __syncthreads();
    if (threadIdx.x == 0) {
        double t = 0.0;
#pragma unroll
        for (int w = 0; w < TPB / 32; ++w) t += s_red[w];
        atomicAdd(&g_loss_acc, t);
        __threadfence();
        unsigned int prev = atomicAdd(&g_done_ctr, 1u);
        if (prev == GRID - 1) {  // last block: finalize loss, reset for next replay
            double m = atomicAdd(&g_loss_acc, 0.0) / (double)((long long)NT * DD);
            float m32 = (float)m;
            out[loss_idx] = __fadd_rn(m32, __fmul_rn(0.25f, m32));
            g_loss_acc = 0.0;
            __threadfence();
            g_done_ctr = 0u;
        }
    }
}

extern "C" void kernel_launch(void* const* d_in, const int* in_sizes, int n_in,
                              void* d_out, int out_size) {
    const float* z;
    const float* cb;
    if (in_sizes[0] == NT * DD) {
        z = (const float*)d_in[0];
        cb = (const float*)d_in[1];
    } else {
        z = (const float*)d_in[1];
        cb = (const float*)d_in[0];
    }
    float* out = (float*)d_out;

    cudaFuncSetAttribute(vq_fused, cudaFuncAttributeMaxDynamicSharedMemorySize,
                         SMEM_BYTES);
    vq_fused<<<GRID, TPB, SMEM_BYTES>>>(z, cb, out, out_size - 1);
}